// round 1
// baseline (speedup 1.0000x reference)
#include <cuda_runtime.h>
#include <cuda_bf16.h>
#include <math.h>

#define N_NODES 50000
#define N_EDGES 600000
#define IN_DIM  128
#define HID     128
#define OUT_DIM 64
#define LN_EPS  1e-5f

// ---------------- scratch (device globals; no allocation allowed) ----------------
__device__ int   g_deg_out[N_NODES];
__device__ int   g_deg_in [N_NODES];
__device__ float g_out_norm[N_NODES];
__device__ float g_in_norm [N_NODES];
__device__ int   g_row_off[N_NODES + 1];
__device__ int   g_cursor [N_NODES];
__device__ int   g_edge_src[N_EDGES];
__device__ float g_tbuf[(size_t)N_NODES * HID];
__device__ float g_hbuf[(size_t)N_NODES * HID];

// ---------------- small setup kernels ----------------
__global__ void init_kernel() {
    int i = blockIdx.x * blockDim.x + threadIdx.x;
    if (i < N_NODES) { g_deg_out[i] = 0; g_deg_in[i] = 0; }
}

__global__ void degree_kernel(const int* __restrict__ src, const int* __restrict__ dst) {
    int e = blockIdx.x * blockDim.x + threadIdx.x;
    if (e < N_EDGES) {
        atomicAdd(&g_deg_out[src[e]], 1);
        atomicAdd(&g_deg_in [dst[e]], 1);
    }
}

__global__ void norm_kernel() {
    int i = blockIdx.x * blockDim.x + threadIdx.x;
    if (i < N_NODES) {
        g_out_norm[i] = rsqrtf(fmaxf((float)g_deg_out[i], 1.0f));
        g_in_norm [i] = rsqrtf(fmaxf((float)g_deg_in [i], 1.0f));
    }
}

// single-block exclusive scan of g_deg_in -> g_row_off, g_cursor
__global__ void scan_kernel() {
    __shared__ int warp_sums[32];
    int tid  = threadIdx.x;
    int lane = tid & 31, wid = tid >> 5;
    int carry = 0;
    for (int base = 0; base < N_NODES; base += 1024) {
        int i = base + tid;
        int v = (i < N_NODES) ? g_deg_in[i] : 0;
        int x = v;
        #pragma unroll
        for (int off = 1; off < 32; off <<= 1) {
            int y = __shfl_up_sync(0xFFFFFFFFu, x, off);
            if (lane >= off) x += y;
        }
        if (lane == 31) warp_sums[wid] = x;
        __syncthreads();
        if (wid == 0) {
            int w = warp_sums[lane];
            #pragma unroll
            for (int off = 1; off < 32; off <<= 1) {
                int y = __shfl_up_sync(0xFFFFFFFFu, w, off);
                if (lane >= off) w += y;
            }
            warp_sums[lane] = w;
        }
        __syncthreads();
        int prefix = carry + (wid > 0 ? warp_sums[wid - 1] : 0) + (x - v);
        if (i < N_NODES) { g_row_off[i] = prefix; g_cursor[i] = prefix; }
        carry += warp_sums[31];
        __syncthreads();
    }
    if (tid == 0) g_row_off[N_NODES] = carry;
}

__global__ void fill_kernel(const int* __restrict__ src, const int* __restrict__ dst) {
    int e = blockIdx.x * blockDim.x + threadIdx.x;
    if (e < N_EDGES) {
        int d = dst[e];
        int pos = atomicAdd(&g_cursor[d], 1);
        g_edge_src[pos] = src[e];
    }
}

// ---------------- GEMM: T[row,:] = (H[row,:] * out_norm[row]) @ W  ----------------
// K = 128 fixed. Tile: 64 rows x DOUT cols, 256 threads, K chunked by 32 (<=48KB smem).
template <int DOUT>
__global__ void gemm_kernel(const float* __restrict__ H, const float* __restrict__ W,
                            float* __restrict__ T) {
    constexpr int TM = 64, KC = 32, K = 128;
    constexpr int COLG = DOUT / 8;          // 16 (128) or 8 (64)
    constexpr int RP   = TM / (256 / COLG); // 4 (128)  or 2 (64)

    __shared__ float As[TM * KC];
    __shared__ float Bs[KC * DOUT];

    int tid  = threadIdx.x;
    int row0 = blockIdx.x * TM;
    int tx = tid % COLG, ty = tid / COLG;
    int c0 = tx * 8;

    float acc[RP][8];
    #pragma unroll
    for (int i = 0; i < RP; ++i)
        #pragma unroll
        for (int j = 0; j < 8; ++j) acc[i][j] = 0.0f;

    for (int kc = 0; kc < K; kc += KC) {
        // load A chunk (scaled by out_norm), 512 float4s / 256 threads
        #pragma unroll
        for (int j = 0; j < (TM * KC / 4) / 256; ++j) {
            int idx = tid + j * 256;
            int r = idx / (KC / 4), k4 = idx % (KC / 4);
            int row = row0 + r;
            float4 v = make_float4(0.f, 0.f, 0.f, 0.f);
            float nrm = 0.f;
            if (row < N_NODES) {
                v = *(const float4*)&H[(size_t)row * K + kc + k4 * 4];
                nrm = g_out_norm[row];
            }
            *(float4*)&As[r * KC + k4 * 4] =
                make_float4(v.x * nrm, v.y * nrm, v.z * nrm, v.w * nrm);
        }
        // load B chunk
        #pragma unroll
        for (int j = 0; j < (KC * DOUT / 4) / 256; ++j) {
            int idx = tid + j * 256;
            int k = idx / (DOUT / 4), c4 = idx % (DOUT / 4);
            *(float4*)&Bs[k * DOUT + c4 * 4] =
                *(const float4*)&W[(size_t)(kc + k) * DOUT + c4 * 4];
        }
        __syncthreads();

        #pragma unroll
        for (int k4 = 0; k4 < KC / 4; ++k4) {
            float4 a4[RP];
            #pragma unroll
            for (int i = 0; i < RP; ++i)
                a4[i] = *(const float4*)&As[(ty * RP + i) * KC + k4 * 4];
            #pragma unroll
            for (int kk = 0; kk < 4; ++kk) {
                float4 b0 = *(const float4*)&Bs[(k4 * 4 + kk) * DOUT + c0];
                float4 b1 = *(const float4*)&Bs[(k4 * 4 + kk) * DOUT + c0 + 4];
                #pragma unroll
                for (int i = 0; i < RP; ++i) {
                    float av = ((const float*)&a4[i])[kk];
                    acc[i][0] += av * b0.x; acc[i][1] += av * b0.y;
                    acc[i][2] += av * b0.z; acc[i][3] += av * b0.w;
                    acc[i][4] += av * b1.x; acc[i][5] += av * b1.y;
                    acc[i][6] += av * b1.z; acc[i][7] += av * b1.w;
                }
            }
        }
        __syncthreads();
    }

    #pragma unroll
    for (int i = 0; i < RP; ++i) {
        int row = row0 + ty * RP + i;
        if (row < N_NODES) {
            *(float4*)&T[(size_t)row * DOUT + c0] =
                make_float4(acc[i][0], acc[i][1], acc[i][2], acc[i][3]);
            *(float4*)&T[(size_t)row * DOUT + c0 + 4] =
                make_float4(acc[i][4], acc[i][5], acc[i][6], acc[i][7]);
        }
    }
}

// ---------------- aggregate: out[v] = epi( sum_{e in in(v)} T[src_e] * in_norm[v] + b ) ----
// blockDim.x == D, blockDim.y nodes per block (1 when LN).
template <int D, bool LN>
__global__ void aggregate_kernel(const float* __restrict__ T, float* __restrict__ out,
                                 const float* __restrict__ bias,
                                 const float* __restrict__ ln_scale,
                                 const float* __restrict__ ln_bias) {
    int v = blockIdx.x * blockDim.y + threadIdx.y;
    int tid = threadIdx.x;
    const int s = g_row_off[v], e = g_row_off[v + 1];

    float acc = 0.0f;
    int i = s;
    for (; i + 4 <= e; i += 4) {
        int u0 = g_edge_src[i + 0];
        int u1 = g_edge_src[i + 1];
        int u2 = g_edge_src[i + 2];
        int u3 = g_edge_src[i + 3];
        float v0 = T[(size_t)u0 * D + tid];
        float v1 = T[(size_t)u1 * D + tid];
        float v2 = T[(size_t)u2 * D + tid];
        float v3 = T[(size_t)u3 * D + tid];
        acc += v0; acc += v1; acc += v2; acc += v3;
    }
    for (; i < e; ++i) acc += T[(size_t)g_edge_src[i] * D + tid];

    float val = fmaxf(acc * g_in_norm[v] + bias[tid], 0.0f);

    if (LN) {
        constexpr int NW = D / 32;
        float s1 = val, s2 = val * val;
        #pragma unroll
        for (int off = 16; off > 0; off >>= 1) {
            s1 += __shfl_xor_sync(0xFFFFFFFFu, s1, off);
            s2 += __shfl_xor_sync(0xFFFFFFFFu, s2, off);
        }
        __shared__ float sh1[NW], sh2[NW];
        int w = tid >> 5;
        if ((tid & 31) == 0) { sh1[w] = s1; sh2[w] = s2; }
        __syncthreads();
        float t1 = 0.f, t2 = 0.f;
        #pragma unroll
        for (int j = 0; j < NW; ++j) { t1 += sh1[j]; t2 += sh2[j]; }
        float mu  = t1 * (1.0f / D);
        float var = t2 * (1.0f / D) - mu * mu;
        val = (val - mu) * rsqrtf(var + LN_EPS) * ln_scale[tid] + ln_bias[tid];
    }
    out[(size_t)v * D + tid] = val;
}

// ---------------- launch ----------------
extern "C" void kernel_launch(void* const* d_in, const int* in_sizes, int n_in,
                              void* d_out, int out_size) {
    const float* x        = (const float*)d_in[0];
    const int*   src      = (const int*)  d_in[1];
    const int*   dst      = (const int*)  d_in[2];
    const float* W0       = (const float*)d_in[3];
    const float* b0       = (const float*)d_in[4];
    const float* W1       = (const float*)d_in[5];
    const float* b1       = (const float*)d_in[6];
    const float* W2       = (const float*)d_in[7];
    const float* b2       = (const float*)d_in[8];
    const float* ln_scale = (const float*)d_in[9];
    const float* ln_bias  = (const float*)d_in[10];
    float* out = (float*)d_out;

    float* tbuf; cudaGetSymbolAddress((void**)&tbuf, g_tbuf);
    float* hbuf; cudaGetSymbolAddress((void**)&hbuf, g_hbuf);

    const int EBLK = (N_EDGES + 255) / 256;
    const int NBLK = (N_NODES + 255) / 256;
    const int GBLK = (N_NODES + 63) / 64;

    // graph preprocessing (recomputed every call; deterministic work)
    init_kernel  <<<NBLK, 256>>>();
    degree_kernel<<<EBLK, 256>>>(src, dst);
    norm_kernel  <<<NBLK, 256>>>();
    scan_kernel  <<<1, 1024>>>();
    fill_kernel  <<<EBLK, 256>>>(src, dst);

    // layer 0: x -> tbuf -> hbuf (relu + LN)
    gemm_kernel<HID><<<GBLK, 256>>>(x, W0, tbuf);
    aggregate_kernel<HID, true><<<N_NODES, dim3(HID, 1)>>>(tbuf, hbuf, b0, ln_scale, ln_bias);

    // layer 1: hbuf -> tbuf -> hbuf (relu + LN)
    gemm_kernel<HID><<<GBLK, 256>>>(hbuf, W1, tbuf);
    aggregate_kernel<HID, true><<<N_NODES, dim3(HID, 1)>>>(tbuf, hbuf, b1, ln_scale, ln_bias);

    // layer 2: hbuf -> tbuf -> out (relu, no LN)
    gemm_kernel<OUT_DIM><<<GBLK, 256>>>(hbuf, W2, tbuf);
    aggregate_kernel<OUT_DIM, false><<<N_NODES / 2, dim3(OUT_DIM, 2)>>>(tbuf, out, b2, ln_scale, ln_bias);

    (void)in_sizes; (void)n_in; (void)out_size;
}